// round 9
// baseline (speedup 1.0000x reference)
#include <cuda_runtime.h>
#include <cuda_fp16.h>
#include <cstdint>

#define B_   4
#define S_   2048
#define HID_ 1024
#define NHD_ 1024
#define EPS_ 1e-6f

// ---------------------------------------------------------------------------
// Scratch (allocation-free rule: device globals only)  ~88 MB
// ---------------------------------------------------------------------------
__device__ __half g_hs_h[(size_t)B_ * S_ * HID_];
__device__ __half g_wv_h[(size_t)HID_ * NHD_];
__device__ __half g_wv_l[(size_t)HID_ * NHD_];
__device__ __half g_at_h[(size_t)B_ * S_ * S_];
__device__ __half g_v_h[(size_t)B_ * S_ * NHD_];
__device__ __half g_v_l[(size_t)B_ * S_ * NHD_];

// ---------------------------------------------------------------------------
// Helpers (plain-sm_103-legal: cp.async / ldmatrix / mma.sync)
// ---------------------------------------------------------------------------
__device__ __forceinline__ uint32_t smem_u32(const void* p) {
    uint32_t a;
    asm("{ .reg .u64 t; cvta.to.shared.u64 t, %1; cvt.u32.u64 %0, t; }"
        : "=r"(a) : "l"(p));
    return a;
}
__device__ __forceinline__ void cp16(uint32_t dst, const void* src) {
    asm volatile("cp.async.cg.shared.global [%0], [%1], 16;"
                 :: "r"(dst), "l"(src) : "memory");
}
#define CP_COMMIT() asm volatile("cp.async.commit_group;" ::: "memory")
#define CP_WAIT1()  asm volatile("cp.async.wait_group 1;" ::: "memory")

__device__ __forceinline__ void ldsm_x4(uint32_t* r, uint32_t a) {
    asm volatile("ldmatrix.sync.aligned.m8n8.x4.shared.b16 {%0,%1,%2,%3}, [%4];"
                 : "=r"(r[0]), "=r"(r[1]), "=r"(r[2]), "=r"(r[3]) : "r"(a));
}
__device__ __forceinline__ void ldsm_x4_t(uint32_t* r, uint32_t a) {
    asm volatile("ldmatrix.sync.aligned.m8n8.x4.trans.shared.b16 {%0,%1,%2,%3}, [%4];"
                 : "=r"(r[0]), "=r"(r[1]), "=r"(r[2]), "=r"(r[3]) : "r"(a));
}
__device__ __forceinline__ void mma_f16(float* c, const uint32_t* a, const uint32_t* b) {
    asm volatile(
        "mma.sync.aligned.m16n8k16.row.col.f32.f16.f16.f32 "
        "{%0,%1,%2,%3}, {%4,%5,%6,%7}, {%8,%9}, {%0,%1,%2,%3};"
        : "+f"(c[0]), "+f"(c[1]), "+f"(c[2]), "+f"(c[3])
        : "r"(a[0]), "r"(a[1]), "r"(a[2]), "r"(a[3]), "r"(b[0]), "r"(b[1]));
}

__device__ __forceinline__ void split2h(float v, unsigned short& h, unsigned short& l) {
    __half hb = __float2half_rn(v);
    float r = v - __half2float(hb);
    __half lb = __float2half_rn(r);
    h = __half_as_ushort(hb);
    l = __half_as_ushort(lb);
}

// ---------------------------------------------------------------------------
// Prep kernels
// ---------------------------------------------------------------------------
// per-batch: rowsum + normalize + causal mask + fp16 convert
__global__ __launch_bounds__(256) void attn_prep(const float* __restrict__ attn_b,
                                                 __half* __restrict__ out_b) {
    int q = blockIdx.x;                // 0..S-1 within this batch
    const float* a = attn_b + (size_t)q * S_;
    float s = 0.f;
    for (int k = threadIdx.x; k <= q; k += 256) s += a[k];
    #pragma unroll
    for (int o = 16; o; o >>= 1) s += __shfl_down_sync(0xffffffffu, s, o);
    __shared__ float red[8];
    __shared__ float sinv;
    if ((threadIdx.x & 31) == 0) red[threadIdx.x >> 5] = s;
    __syncthreads();
    if (threadIdx.x == 0) {
        float t = 0.f;
        #pragma unroll
        for (int i = 0; i < 8; i++) t += red[i];
        sinv = 1.f / (EPS_ + t);
    }
    __syncthreads();
    float inv = sinv;
    ushort4* H = reinterpret_cast<ushort4*>(out_b + (size_t)q * S_);
    for (int c = threadIdx.x; c < S_ / 4; c += 256) {
        int k = c * 4;
        float4 v = *reinterpret_cast<const float4*>(a + k);
        ushort4 o;
        o.x = __half_as_ushort(__float2half_rn((k + 0 <= q) ? v.x * inv : 0.f));
        o.y = __half_as_ushort(__float2half_rn((k + 1 <= q) ? v.y * inv : 0.f));
        o.z = __half_as_ushort(__float2half_rn((k + 2 <= q) ? v.z * inv : 0.f));
        o.w = __half_as_ushort(__float2half_rn((k + 3 <= q) ? v.w * inv : 0.f));
        H[c] = o;
    }
}

__global__ __launch_bounds__(256) void split_hi(const float* __restrict__ src,
                                                __half* __restrict__ dh) {
    size_t i = (size_t)blockIdx.x * 256 + threadIdx.x;   // float4 index
    float4 v = reinterpret_cast<const float4*>(src)[i];
    ushort4 H;
    H.x = __half_as_ushort(__float2half_rn(v.x));
    H.y = __half_as_ushort(__float2half_rn(v.y));
    H.z = __half_as_ushort(__float2half_rn(v.z));
    H.w = __half_as_ushort(__float2half_rn(v.w));
    reinterpret_cast<ushort4*>(dh)[i] = H;
}

__global__ __launch_bounds__(256) void split_hilo(const float* __restrict__ src,
                                                  __half* __restrict__ dh,
                                                  __half* __restrict__ dl) {
    size_t i = (size_t)blockIdx.x * 256 + threadIdx.x;   // float4 index
    float4 v = reinterpret_cast<const float4*>(src)[i];
    ushort4 H, L;
    split2h(v.x, H.x, L.x); split2h(v.y, H.y, L.y);
    split2h(v.z, H.z, L.z); split2h(v.w, H.w, L.w);
    reinterpret_cast<ushort4*>(dh)[i] = H;
    reinterpret_cast<ushort4*>(dl)[i] = L;
}

// ---------------------------------------------------------------------------
// HMMA GEMM: C[m,n] = sum_k A[m,k] * B[k,n]
// A: fp16 hi-only.  B: fp16 hi+lo (2-product emulation: Ah@Bh + Ah@Bl).
// 128x128 CTA tile, BK=32, 8 warps (64x32 each), 3-stage cp.async pipeline
// with ONE __syncthreads per chunk, 2 CTAs/SM co-residency.
// Smem per stage: Ah[128][80B] Bh[32][272B] Bl[32][272B] = 27648 B
// ---------------------------------------------------------------------------
static constexpr int STG = 27648;
static constexpr int GEMM_SMEM = 3 * STG;   // 82944  (x2 CTAs = 165888 <= 228KB)
static constexpr int OFF_BH = 10240;
static constexpr int OFF_BL = 18944;

template <bool CAUSAL, bool SPLIT_EPI>
__global__ __launch_bounds__(256, 2) void mma_gemm(
    const __half* __restrict__ Ag,
    const __half* __restrict__ Bgh, const __half* __restrict__ Bgl,
    float* __restrict__ Cf, __half* __restrict__ Chi, __half* __restrict__ Clo,
    const float* __restrict__ bias,
    int K, int ldA, int ldB, int ldC) {
    extern __shared__ char dsm[];
    const uint32_t sbase = smem_u32(dsm);
    const int tid = threadIdx.x, lane = tid & 31, wid = tid >> 5;
    const int bx = blockIdx.x;
    const int by = CAUSAL ? (gridDim.y - 1 - blockIdx.y) : blockIdx.y;
    const int m0 = by * 128, n0 = bx * 128;

    const int nk = CAUSAL ? (by + 1) * 4 : (K >> 5);

    auto load_stage = [&](int buf, int chunk) {
        const uint32_t st = sbase + buf * STG;
        const int k0 = chunk * 32;
        // A hi: 128 rows x 64B, 512 x 16B chunks, 2 per thread
        #pragma unroll
        for (int i = 0; i < 2; i++) {
            const int j = tid + 256 * i;
            const int row = j >> 2, c = j & 3;
            cp16(st + row * 80 + c * 16,
                 Ag + (size_t)(m0 + row) * ldA + k0 + c * 8);
        }
        // B hi / lo: 32 rows x 256B, 512 x 16B chunks each, 2 per thread
        #pragma unroll
        for (int i = 0; i < 2; i++) {
            const int j = tid + 256 * i;
            const int row = j >> 4, c = j & 15;
            cp16(st + OFF_BH + row * 272 + c * 16,
                 Bgh + (size_t)(k0 + row) * ldB + n0 + c * 8);
            cp16(st + OFF_BL + row * 272 + c * 16,
                 Bgl + (size_t)(k0 + row) * ldB + n0 + c * 8);
        }
    };

    float acc[4][4][4];
    #pragma unroll
    for (int i = 0; i < 4; i++)
        #pragma unroll
        for (int j = 0; j < 4; j++)
            #pragma unroll
            for (int t = 0; t < 4; t++) acc[i][j][t] = 0.f;

    const int wm = (wid >> 2) * 64;      // warp m-offset within CTA
    const int wn = (wid & 3) * 32;       // warp n-offset within CTA

    // prologue: stages 0,1 (nk >= 4 always)
    load_stage(0, 0); CP_COMMIT();
    load_stage(1, 1); CP_COMMIT();

    for (int kt = 0; kt < nk; kt++) {
        CP_WAIT1();                 // oldest pending group (chunk kt) complete
        __syncthreads();            // all warps past compute of kt-1 -> buffer (kt+2)%3 free
        if (kt + 2 < nk) load_stage((kt + 2) % 3, kt + 2);
        CP_COMMIT();                // always commit (possibly empty group)

        const uint32_t st = sbase + (kt % 3) * STG;
        #pragma unroll
        for (int kk = 0; kk < 2; kk++) {
            const int k16 = kk * 16;
            uint32_t a_r[4][4], b_h[4][2], b_l[4][2];
            #pragma unroll
            for (int mt = 0; mt < 4; mt++) {
                uint32_t off = ((wm + mt * 16 + (lane & 15)) * 80 +
                                (k16 + (lane >> 4) * 8) * 2);
                ldsm_x4(a_r[mt], st + off);
            }
            #pragma unroll
            for (int np = 0; np < 2; np++) {
                uint32_t off = ((k16 + (lane & 15)) * 272 +
                                (wn + np * 16 + (lane >> 4) * 8) * 2);
                uint32_t t4[4];
                ldsm_x4_t(t4, st + OFF_BH + off);
                b_h[np * 2][0] = t4[0]; b_h[np * 2][1] = t4[1];
                b_h[np * 2 + 1][0] = t4[2]; b_h[np * 2 + 1][1] = t4[3];
                ldsm_x4_t(t4, st + OFF_BL + off);
                b_l[np * 2][0] = t4[0]; b_l[np * 2][1] = t4[1];
                b_l[np * 2 + 1][0] = t4[2]; b_l[np * 2 + 1][1] = t4[3];
            }
            #pragma unroll
            for (int mt = 0; mt < 4; mt++)
                #pragma unroll
                for (int nt = 0; nt < 4; nt++) {
                    mma_f16(acc[mt][nt], a_r[mt], b_h[nt]);
                    mma_f16(acc[mt][nt], a_r[mt], b_l[nt]);
                }
        }
    }

    // epilogue
    const int gr = lane >> 2, gc = (lane & 3) * 2;
    #pragma unroll
    for (int mt = 0; mt < 4; mt++) {
        const int mrow = m0 + wm + mt * 16 + gr;
        #pragma unroll
        for (int nt = 0; nt < 4; nt++) {
            const int ncol = n0 + wn + nt * 8 + gc;
            #pragma unroll
            for (int h = 0; h < 2; h++) {
                const int r = mrow + h * 8;
                float v0 = acc[mt][nt][h * 2 + 0];
                float v1 = acc[mt][nt][h * 2 + 1];
                if (SPLIT_EPI) {
                    const float2 bb = *reinterpret_cast<const float2*>(bias + ncol);
                    v0 += bb.x; v1 += bb.y;
                    unsigned short h0, l0, h1, l1;
                    split2h(v0, h0, l0);
                    split2h(v1, h1, l1);
                    uint32_t hp = (uint32_t)h0 | ((uint32_t)h1 << 16);
                    uint32_t lp = (uint32_t)l0 | ((uint32_t)l1 << 16);
                    *reinterpret_cast<uint32_t*>(Chi + (size_t)r * ldC + ncol) = hp;
                    *reinterpret_cast<uint32_t*>(Clo + (size_t)r * ldC + ncol) = lp;
                } else {
                    float2 o; o.x = v0; o.y = v1;
                    *reinterpret_cast<float2*>(Cf + (size_t)r * ldC + ncol) = o;
                }
            }
        }
    }
}

// ---------------------------------------------------------------------------
extern "C" void kernel_launch(void* const* d_in, const int* in_sizes, int n_in,
                              void* d_out, int out_size) {
    const float* hs    = (const float*)d_in[0];   // [B,S,HID]
    const float* assoc = (const float*)d_in[1];   // [B,S,S]
    // d_in[2] = broad_hc_attn (unused: broad_heads == 0)
    const float* Wv    = (const float*)d_in[3];   // [HID, NH*HD]
    const float* bv    = (const float*)d_in[4];   // [NH*HD]
    float*       out   = (float*)d_out;           // [B,S,NH*HD]
    (void)in_sizes; (void)n_in; (void)out_size;

    // one-time streams + events for fork-join overlap (no device memory)
    static cudaStream_t s2 = nullptr, s3 = nullptr;
    static cudaEvent_t evF = nullptr, evDone = nullptr;
    static cudaEvent_t evPrep[B_], evG1[B_];
    if (s2 == nullptr) {
        cudaStreamCreateWithFlags(&s2, cudaStreamNonBlocking);
        cudaStreamCreateWithFlags(&s3, cudaStreamNonBlocking);
        cudaEventCreateWithFlags(&evF, cudaEventDisableTiming);
        cudaEventCreateWithFlags(&evDone, cudaEventDisableTiming);
        for (int b = 0; b < B_; b++) {
            cudaEventCreateWithFlags(&evPrep[b], cudaEventDisableTiming);
            cudaEventCreateWithFlags(&evG1[b], cudaEventDisableTiming);
        }
    }

    cudaFuncSetAttribute(mma_gemm<false, true>,
                         cudaFuncAttributeMaxDynamicSharedMemorySize, GEMM_SMEM);
    cudaFuncSetAttribute(mma_gemm<true, false>,
                         cudaFuncAttributeMaxDynamicSharedMemorySize, GEMM_SMEM);

    __half *hs_h, *wv_h, *wv_l, *at_h, *v_h, *v_l;
    cudaGetSymbolAddress((void**)&hs_h, g_hs_h);
    cudaGetSymbolAddress((void**)&wv_h, g_wv_h);
    cudaGetSymbolAddress((void**)&wv_l, g_wv_l);
    cudaGetSymbolAddress((void**)&at_h, g_at_h);
    cudaGetSymbolAddress((void**)&v_h, g_v_h);
    cudaGetSymbolAddress((void**)&v_l, g_v_l);

    const size_t SS = (size_t)S_ * S_;        // attn per-batch elems
    const size_t SV = (size_t)S_ * NHD_;      // value/out per-batch elems
    const size_t SH = (size_t)S_ * HID_;      // hidden per-batch elems

    // fork: per-batch attn prep on side stream s2
    cudaEventRecord(evF, 0);
    cudaStreamWaitEvent(s2, evF, 0);
    for (int b = 0; b < B_; b++) {
        attn_prep<<<S_, 256, 0, s2>>>(assoc + b * SS, at_h + b * SS);
        cudaEventRecord(evPrep[b], s2);
    }

    // main stream: splits, then per-batch GEMM1
    split_hilo<<<(int)(((size_t)HID_ * NHD_ / 4) / 256), 256>>>(Wv, wv_h, wv_l);
    split_hi<<<(int)(((size_t)B_ * S_ * HID_ / 4) / 256), 256>>>(hs, hs_h);
    for (int b = 0; b < B_; b++) {
        mma_gemm<false, true><<<dim3(NHD_ / 128, S_ / 128, 1), 256, GEMM_SMEM>>>(
            hs_h + b * SH, wv_h, wv_l, nullptr, v_h + b * SV, v_l + b * SV, bv,
            HID_, HID_, NHD_, NHD_);
        cudaEventRecord(evG1[b], 0);
    }

    // s3: per-batch GEMM2 as soon as its inputs are ready (overlaps GEMM1 b+1)
    for (int b = 0; b < B_; b++) {
        cudaStreamWaitEvent(s3, evG1[b], 0);
        cudaStreamWaitEvent(s3, evPrep[b], 0);
        mma_gemm<true, false><<<dim3(NHD_ / 128, S_ / 128, 1), 256, GEMM_SMEM, s3>>>(
            at_h + b * SS, v_h + b * SV, v_l + b * SV, out + b * SV,
            nullptr, nullptr, nullptr,
            S_, S_, NHD_, NHD_);
    }
    cudaEventRecord(evDone, s3);
    cudaStreamWaitEvent(0, evDone, 0);
}

// round 10
// speedup vs baseline: 1.3626x; 1.3626x over previous
#include <cuda_runtime.h>
#include <cuda_fp16.h>
#include <cstdint>

#define B_   4
#define S_   2048
#define HID_ 1024
#define NHD_ 1024
#define EPS_ 1e-6f

// ---------------------------------------------------------------------------
// Scratch (allocation-free rule: device globals only)  ~88 MB
// ---------------------------------------------------------------------------
__device__ __half g_hs_h[(size_t)B_ * S_ * HID_];
__device__ __half g_wv_h[(size_t)HID_ * NHD_];
__device__ __half g_wv_l[(size_t)HID_ * NHD_];
__device__ __half g_at_h[(size_t)B_ * S_ * S_];
__device__ __half g_v_h[(size_t)B_ * S_ * NHD_];
__device__ __half g_v_l[(size_t)B_ * S_ * NHD_];

// ---------------------------------------------------------------------------
// Helpers (plain-sm_103-legal: cp.async / ldmatrix / mma.sync)
// ---------------------------------------------------------------------------
__device__ __forceinline__ uint32_t smem_u32(const void* p) {
    uint32_t a;
    asm("{ .reg .u64 t; cvta.to.shared.u64 t, %1; cvt.u32.u64 %0, t; }"
        : "=r"(a) : "l"(p));
    return a;
}
__device__ __forceinline__ void cp16(uint32_t dst, const void* src) {
    asm volatile("cp.async.cg.shared.global [%0], [%1], 16;"
                 :: "r"(dst), "l"(src) : "memory");
}
#define CP_COMMIT() asm volatile("cp.async.commit_group;" ::: "memory")
#define CP_WAIT1()  asm volatile("cp.async.wait_group 1;" ::: "memory")

__device__ __forceinline__ void ldsm_x4(uint32_t* r, uint32_t a) {
    asm volatile("ldmatrix.sync.aligned.m8n8.x4.shared.b16 {%0,%1,%2,%3}, [%4];"
                 : "=r"(r[0]), "=r"(r[1]), "=r"(r[2]), "=r"(r[3]) : "r"(a));
}
__device__ __forceinline__ void ldsm_x4_t(uint32_t* r, uint32_t a) {
    asm volatile("ldmatrix.sync.aligned.m8n8.x4.trans.shared.b16 {%0,%1,%2,%3}, [%4];"
                 : "=r"(r[0]), "=r"(r[1]), "=r"(r[2]), "=r"(r[3]) : "r"(a));
}
__device__ __forceinline__ void mma_f16(float* c, const uint32_t* a, const uint32_t* b) {
    asm volatile(
        "mma.sync.aligned.m16n8k16.row.col.f32.f16.f16.f32 "
        "{%0,%1,%2,%3}, {%4,%5,%6,%7}, {%8,%9}, {%0,%1,%2,%3};"
        : "+f"(c[0]), "+f"(c[1]), "+f"(c[2]), "+f"(c[3])
        : "r"(a[0]), "r"(a[1]), "r"(a[2]), "r"(a[3]), "r"(b[0]), "r"(b[1]));
}

__device__ __forceinline__ void split2h(float v, unsigned short& h, unsigned short& l) {
    __half hb = __float2half_rn(v);
    float r = v - __half2float(hb);
    __half lb = __float2half_rn(r);
    h = __half_as_ushort(hb);
    l = __half_as_ushort(lb);
}

// ---------------------------------------------------------------------------
// Prep kernels
// ---------------------------------------------------------------------------
__global__ __launch_bounds__(256) void attn_prep(const float* __restrict__ attn) {
    int row = blockIdx.x;              // b*S + q
    int q   = row & (S_ - 1);
    const float* a = attn + (size_t)row * S_;
    float s = 0.f;
    for (int k = threadIdx.x; k <= q; k += 256) s += a[k];
    #pragma unroll
    for (int o = 16; o; o >>= 1) s += __shfl_down_sync(0xffffffffu, s, o);
    __shared__ float red[8];
    __shared__ float sinv;
    if ((threadIdx.x & 31) == 0) red[threadIdx.x >> 5] = s;
    __syncthreads();
    if (threadIdx.x == 0) {
        float t = 0.f;
        #pragma unroll
        for (int i = 0; i < 8; i++) t += red[i];
        sinv = 1.f / (EPS_ + t);
    }
    __syncthreads();
    float inv = sinv;
    ushort4* H = reinterpret_cast<ushort4*>(g_at_h + (size_t)row * S_);
    for (int c = threadIdx.x; c < S_ / 4; c += 256) {
        int k = c * 4;
        float4 v = *reinterpret_cast<const float4*>(a + k);
        ushort4 o;
        o.x = __half_as_ushort(__float2half_rn((k + 0 <= q) ? v.x * inv : 0.f));
        o.y = __half_as_ushort(__float2half_rn((k + 1 <= q) ? v.y * inv : 0.f));
        o.z = __half_as_ushort(__float2half_rn((k + 2 <= q) ? v.z * inv : 0.f));
        o.w = __half_as_ushort(__float2half_rn((k + 3 <= q) ? v.w * inv : 0.f));
        H[c] = o;
    }
}

__global__ __launch_bounds__(256) void split_hi(const float* __restrict__ src,
                                                __half* __restrict__ dh) {
    size_t i = (size_t)blockIdx.x * 256 + threadIdx.x;   // float4 index
    float4 v = reinterpret_cast<const float4*>(src)[i];
    ushort4 H;
    H.x = __half_as_ushort(__float2half_rn(v.x));
    H.y = __half_as_ushort(__float2half_rn(v.y));
    H.z = __half_as_ushort(__float2half_rn(v.z));
    H.w = __half_as_ushort(__float2half_rn(v.w));
    reinterpret_cast<ushort4*>(dh)[i] = H;
}

__global__ __launch_bounds__(256) void split_hilo(const float* __restrict__ src,
                                                  __half* __restrict__ dh,
                                                  __half* __restrict__ dl) {
    size_t i = (size_t)blockIdx.x * 256 + threadIdx.x;   // float4 index
    float4 v = reinterpret_cast<const float4*>(src)[i];
    ushort4 H, L;
    split2h(v.x, H.x, L.x); split2h(v.y, H.y, L.y);
    split2h(v.z, H.z, L.z); split2h(v.w, H.w, L.w);
    reinterpret_cast<ushort4*>(dh)[i] = H;
    reinterpret_cast<ushort4*>(dl)[i] = L;
}

// ---------------------------------------------------------------------------
// HMMA GEMM: C[m,n] = sum_k A[m,k] * B[k,n]
// A: fp16 hi-only.  B: fp16 hi+lo (2-product emulation: Ah@Bh + Ah@Bl).
// 128x128 CTA tile, BK=64, 8 warps (64x32 each), 2-stage cp.async pipeline,
// 2 CTAs/SM co-residency. 128 uninterrupted MMAs/warp between barriers.
// Smem/stage: A as 2x[128][80B] sub-tiles (k0-31, k32-63), Bh[64][272B],
//             Bl[64][272B]  = 55296 B.  2 stages x 2 CTAs = 221184 B/SM.
// ---------------------------------------------------------------------------
static constexpr int OFF_A1 = 10240;
static constexpr int OFF_BH = 20480;
static constexpr int OFF_BL = 37888;
static constexpr int STG = 55296;
static constexpr int GEMM_SMEM = 2 * STG;   // 110592

template <bool CAUSAL, bool SPLIT_EPI>
__global__ __launch_bounds__(256, 2) void mma_gemm(
    const __half* __restrict__ Ag,
    const __half* __restrict__ Bgh, const __half* __restrict__ Bgl,
    float* __restrict__ Cf, __half* __restrict__ Chi, __half* __restrict__ Clo,
    const float* __restrict__ bias,
    int K, int ldA, int ldB, int ldC,
    size_t strA, size_t strB, size_t strC) {
    extern __shared__ char dsm[];
    const uint32_t sbase = smem_u32(dsm);
    const int tid = threadIdx.x, lane = tid & 31, wid = tid >> 5;
    const int bx = blockIdx.x;
    const int by = CAUSAL ? (gridDim.y - 1 - blockIdx.y) : blockIdx.y;
    const int bz = blockIdx.z;
    const int m0 = by * 128, n0 = bx * 128;

    Ag  += (size_t)bz * strA;
    Bgh += (size_t)bz * strB;
    Bgl += (size_t)bz * strB;

    const int nk = CAUSAL ? (by + 1) * 2 : (K >> 6);   // 64-k chunks

    auto load_stage = [&](int buf, int chunk) {
        const uint32_t st = sbase + buf * STG;
        const int k0 = chunk * 64;
        // A hi: 128 rows x 128B, as two 64B sub-tiles; 1024 x 16B, 4/thread
        #pragma unroll
        for (int i = 0; i < 4; i++) {
            const int j = tid + 256 * i;
            const int row = j >> 3, c = j & 7;           // c: 16B chunk in row
            const int sub = c >> 2, cc = c & 3;          // k-half, chunk within
            cp16(st + sub * OFF_A1 + row * 80 + cc * 16,
                 Ag + (size_t)(m0 + row) * ldA + k0 + sub * 32 + cc * 8);
        }
        // B hi / lo: 64 rows x 256B; 1024 x 16B each, 4/thread each
        #pragma unroll
        for (int i = 0; i < 4; i++) {
            const int j = tid + 256 * i;
            const int row = j >> 4, c = j & 15;
            cp16(st + OFF_BH + row * 272 + c * 16,
                 Bgh + (size_t)(k0 + row) * ldB + n0 + c * 8);
            cp16(st + OFF_BL + row * 272 + c * 16,
                 Bgl + (size_t)(k0 + row) * ldB + n0 + c * 8);
        }
    };

    float acc[4][4][4];
    #pragma unroll
    for (int i = 0; i < 4; i++)
        #pragma unroll
        for (int j = 0; j < 4; j++)
            #pragma unroll
            for (int t = 0; t < 4; t++) acc[i][j][t] = 0.f;

    const int wm = (wid >> 2) * 64;      // warp m-offset within CTA
    const int wn = (wid & 3) * 32;       // warp n-offset within CTA

    // prologue: both stages (nk >= 2 always)
    load_stage(0, 0); CP_COMMIT();
    load_stage(1, 1); CP_COMMIT();

    for (int kt = 0; kt < nk; kt++) {
        CP_WAIT1();                 // chunk kt resident
        __syncthreads();

        const uint32_t st = sbase + (kt & 1) * STG;
        #pragma unroll
        for (int kk = 0; kk < 4; kk++) {                 // 4 x k16 per chunk
            const int sub = kk >> 1;                     // A k-half sub-tile
            const int k16 = (kk & 1) * 16;               // k16 within sub-tile
            const int bk16 = kk * 16;                    // k16 within B tile
            uint32_t a_r[4][4], b_h[4][2], b_l[4][2];
            #pragma unroll
            for (int mt = 0; mt < 4; mt++) {
                uint32_t off = sub * OFF_A1 +
                               ((wm + mt * 16 + (lane & 15)) * 80 +
                                (k16 + (lane >> 4) * 8) * 2);
                ldsm_x4(a_r[mt], st + off);
            }
            #pragma unroll
            for (int np = 0; np < 2; np++) {
                uint32_t off = ((bk16 + (lane & 15)) * 272 +
                                (wn + np * 16 + (lane >> 4) * 8) * 2);
                uint32_t t4[4];
                ldsm_x4_t(t4, st + OFF_BH + off);
                b_h[np * 2][0] = t4[0]; b_h[np * 2][1] = t4[1];
                b_h[np * 2 + 1][0] = t4[2]; b_h[np * 2 + 1][1] = t4[3];
                ldsm_x4_t(t4, st + OFF_BL + off);
                b_l[np * 2][0] = t4[0]; b_l[np * 2][1] = t4[1];
                b_l[np * 2 + 1][0] = t4[2]; b_l[np * 2 + 1][1] = t4[3];
            }
            #pragma unroll
            for (int mt = 0; mt < 4; mt++)
                #pragma unroll
                for (int nt = 0; nt < 4; nt++) {
                    mma_f16(acc[mt][nt], a_r[mt], b_h[nt]);
                    mma_f16(acc[mt][nt], a_r[mt], b_l[nt]);
                }
        }
        __syncthreads();            // stage fully consumed before refill
        if (kt + 2 < nk) load_stage(kt & 1, kt + 2);
        CP_COMMIT();                // always commit (possibly empty group)
    }

    // epilogue
    const int gr = lane >> 2, gc = (lane & 3) * 2;
    #pragma unroll
    for (int mt = 0; mt < 4; mt++) {
        const int mrow = m0 + wm + mt * 16 + gr;
        #pragma unroll
        for (int nt = 0; nt < 4; nt++) {
            const int ncol = n0 + wn + nt * 8 + gc;
            #pragma unroll
            for (int h = 0; h < 2; h++) {
                const int r = mrow + h * 8;
                float v0 = acc[mt][nt][h * 2 + 0];
                float v1 = acc[mt][nt][h * 2 + 1];
                if (SPLIT_EPI) {
                    const float2 bb = *reinterpret_cast<const float2*>(bias + ncol);
                    v0 += bb.x; v1 += bb.y;
                    unsigned short h0, l0, h1, l1;
                    split2h(v0, h0, l0);
                    split2h(v1, h1, l1);
                    uint32_t hp = (uint32_t)h0 | ((uint32_t)h1 << 16);
                    uint32_t lp = (uint32_t)l0 | ((uint32_t)l1 << 16);
                    *reinterpret_cast<uint32_t*>(Chi + (size_t)r * ldC + ncol) = hp;
                    *reinterpret_cast<uint32_t*>(Clo + (size_t)r * ldC + ncol) = lp;
                } else {
                    float2 o; o.x = v0; o.y = v1;
                    *reinterpret_cast<float2*>(Cf + (size_t)bz * strC +
                                               (size_t)r * ldC + ncol) = o;
                }
            }
        }
    }
}

// ---------------------------------------------------------------------------
extern "C" void kernel_launch(void* const* d_in, const int* in_sizes, int n_in,
                              void* d_out, int out_size) {
    const float* hs    = (const float*)d_in[0];   // [B,S,HID]
    const float* assoc = (const float*)d_in[1];   // [B,S,S]
    // d_in[2] = broad_hc_attn (unused: broad_heads == 0)
    const float* Wv    = (const float*)d_in[3];   // [HID, NH*HD]
    const float* bv    = (const float*)d_in[4];   // [NH*HD]
    float*       out   = (float*)d_out;           // [B,S,NH*HD]
    (void)in_sizes; (void)n_in; (void)out_size;

    // one-time side stream + events for fork-join overlap (no device memory)
    static cudaStream_t s2 = nullptr;
    static cudaEvent_t ev1 = nullptr, ev2 = nullptr;
    if (s2 == nullptr) {
        cudaStreamCreateWithFlags(&s2, cudaStreamNonBlocking);
        cudaEventCreateWithFlags(&ev1, cudaEventDisableTiming);
        cudaEventCreateWithFlags(&ev2, cudaEventDisableTiming);
    }

    cudaFuncSetAttribute(mma_gemm<false, true>,
                         cudaFuncAttributeMaxDynamicSharedMemorySize, GEMM_SMEM);
    cudaFuncSetAttribute(mma_gemm<true, false>,
                         cudaFuncAttributeMaxDynamicSharedMemorySize, GEMM_SMEM);

    __half *hs_h, *wv_h, *wv_l, *at_h, *v_h, *v_l;
    cudaGetSymbolAddress((void**)&hs_h, g_hs_h);
    cudaGetSymbolAddress((void**)&wv_h, g_wv_h);
    cudaGetSymbolAddress((void**)&wv_l, g_wv_l);
    cudaGetSymbolAddress((void**)&at_h, g_at_h);
    cudaGetSymbolAddress((void**)&v_h, g_v_h);
    cudaGetSymbolAddress((void**)&v_l, g_v_l);

    // fork: attn prep (rowsum + normalize + mask + fp16) on side stream,
    // overlapped with the GEMM1 dependency chain on the main stream.
    cudaEventRecord(ev1, 0);
    cudaStreamWaitEvent(s2, ev1, 0);
    attn_prep<<<B_ * S_, 256, 0, s2>>>(assoc);
    cudaEventRecord(ev2, s2);

    // main stream: hs hi-split, Wv hi/lo split, GEMM1 (full batched grid)
    split_hi<<<(int)(((size_t)B_ * S_ * HID_ / 4) / 256), 256>>>(hs, hs_h);
    split_hilo<<<(int)(((size_t)HID_ * NHD_ / 4) / 256), 256>>>(Wv, wv_h, wv_l);
    mma_gemm<false, true><<<dim3(NHD_ / 128, (B_ * S_) / 128, 1), 256, GEMM_SMEM>>>(
        hs_h, wv_h, wv_l, nullptr, v_h, v_l, bv,
        HID_, HID_, NHD_, NHD_, 0, 0, 0);

    // join, then GEMM2 (causal k-truncation, heavy blocks first)
    cudaStreamWaitEvent(0, ev2, 0);
    mma_gemm<true, false><<<dim3(NHD_ / 128, S_ / 128, B_), 256, GEMM_SMEM>>>(
        at_h, v_h, v_l, out, nullptr, nullptr, nullptr,
        S_, S_, NHD_, NHD_,
        (size_t)S_ * S_, (size_t)S_ * NHD_, (size_t)S_ * NHD_);
}

// round 11
// speedup vs baseline: 2.0733x; 1.5216x over previous
#include <cuda_runtime.h>
#include <cuda_fp16.h>
#include <cstdint>

#define B_   4
#define S_   2048
#define HID_ 1024
#define NHD_ 1024
#define EPS_ 1e-6f

// ---------------------------------------------------------------------------
// Scratch (allocation-free rule: device globals only)  ~58 MB
// ---------------------------------------------------------------------------
__device__ __half g_hs_h[(size_t)B_ * S_ * HID_];
__device__ __half g_wv_h[(size_t)HID_ * NHD_];
__device__ __half g_at_h[(size_t)B_ * S_ * S_];
__device__ __half g_v_h[(size_t)B_ * S_ * NHD_];

// ---------------------------------------------------------------------------
// Helpers (plain-sm_103-legal: cp.async / ldmatrix / mma.sync)
// ---------------------------------------------------------------------------
__device__ __forceinline__ uint32_t smem_u32(const void* p) {
    uint32_t a;
    asm("{ .reg .u64 t; cvta.to.shared.u64 t, %1; cvt.u32.u64 %0, t; }"
        : "=r"(a) : "l"(p));
    return a;
}
__device__ __forceinline__ void cp16(uint32_t dst, const void* src) {
    asm volatile("cp.async.cg.shared.global [%0], [%1], 16;"
                 :: "r"(dst), "l"(src) : "memory");
}
#define CP_COMMIT() asm volatile("cp.async.commit_group;" ::: "memory")
#define CP_WAIT1()  asm volatile("cp.async.wait_group 1;" ::: "memory")

__device__ __forceinline__ void ldsm_x4(uint32_t* r, uint32_t a) {
    asm volatile("ldmatrix.sync.aligned.m8n8.x4.shared.b16 {%0,%1,%2,%3}, [%4];"
                 : "=r"(r[0]), "=r"(r[1]), "=r"(r[2]), "=r"(r[3]) : "r"(a));
}
__device__ __forceinline__ void ldsm_x4_t(uint32_t* r, uint32_t a) {
    asm volatile("ldmatrix.sync.aligned.m8n8.x4.trans.shared.b16 {%0,%1,%2,%3}, [%4];"
                 : "=r"(r[0]), "=r"(r[1]), "=r"(r[2]), "=r"(r[3]) : "r"(a));
}
__device__ __forceinline__ void mma_f16(float* c, const uint32_t* a, const uint32_t* b) {
    asm volatile(
        "mma.sync.aligned.m16n8k16.row.col.f32.f16.f16.f32 "
        "{%0,%1,%2,%3}, {%4,%5,%6,%7}, {%8,%9}, {%0,%1,%2,%3};"
        : "+f"(c[0]), "+f"(c[1]), "+f"(c[2]), "+f"(c[3])
        : "r"(a[0]), "r"(a[1]), "r"(a[2]), "r"(a[3]), "r"(b[0]), "r"(b[1]));
}

// ---------------------------------------------------------------------------
// Prep kernels
// ---------------------------------------------------------------------------
__global__ __launch_bounds__(256) void attn_prep(const float* __restrict__ attn) {
    int row = blockIdx.x;              // b*S + q
    int q   = row & (S_ - 1);
    const float* a = attn + (size_t)row * S_;
    float s = 0.f;
    for (int k = threadIdx.x; k <= q; k += 256) s += a[k];
    #pragma unroll
    for (int o = 16; o; o >>= 1) s += __shfl_down_sync(0xffffffffu, s, o);
    __shared__ float red[8];
    __shared__ float sinv;
    if ((threadIdx.x & 31) == 0) red[threadIdx.x >> 5] = s;
    __syncthreads();
    if (threadIdx.x == 0) {
        float t = 0.f;
        #pragma unroll
        for (int i = 0; i < 8; i++) t += red[i];
        sinv = 1.f / (EPS_ + t);
    }
    __syncthreads();
    float inv = sinv;
    ushort4* H = reinterpret_cast<ushort4*>(g_at_h + (size_t)row * S_);
    for (int c = threadIdx.x; c < S_ / 4; c += 256) {
        int k = c * 4;
        float4 v = *reinterpret_cast<const float4*>(a + k);
        ushort4 o;
        o.x = __half_as_ushort(__float2half_rn((k + 0 <= q) ? v.x * inv : 0.f));
        o.y = __half_as_ushort(__float2half_rn((k + 1 <= q) ? v.y * inv : 0.f));
        o.z = __half_as_ushort(__float2half_rn((k + 2 <= q) ? v.z * inv : 0.f));
        o.w = __half_as_ushort(__float2half_rn((k + 3 <= q) ? v.w * inv : 0.f));
        H[c] = o;
    }
}

__global__ __launch_bounds__(256) void split_hi(const float* __restrict__ src,
                                                __half* __restrict__ dh) {
    size_t i = (size_t)blockIdx.x * 256 + threadIdx.x;   // float4 index
    float4 v = reinterpret_cast<const float4*>(src)[i];
    ushort4 H;
    H.x = __half_as_ushort(__float2half_rn(v.x));
    H.y = __half_as_ushort(__float2half_rn(v.y));
    H.z = __half_as_ushort(__float2half_rn(v.z));
    H.w = __half_as_ushort(__float2half_rn(v.w));
    reinterpret_cast<ushort4*>(dh)[i] = H;
}

// ---------------------------------------------------------------------------
// HMMA GEMM: C[m,n] = sum_k A[m,k] * B[k,n]   (plain fp16, fp32 accumulate)
// 128x128 CTA tile, BK=64, 8 warps (64x32 each), 2-stage cp.async pipeline,
// 2 CTAs/SM co-residency.
// Smem/stage: A as 2x[128][80B] sub-tiles (k0-31, k32-63), B[64][272B]
//             = 37888 B.  2 stages x 2 CTAs = 151552 B/SM.
// ---------------------------------------------------------------------------
static constexpr int OFF_A1 = 10240;
static constexpr int OFF_B  = 20480;
static constexpr int STG = 37888;
static constexpr int GEMM_SMEM = 2 * STG;   // 75776

template <bool CAUSAL, bool HALF_EPI>
__global__ __launch_bounds__(256, 2) void mma_gemm(
    const __half* __restrict__ Ag, const __half* __restrict__ Bg,
    float* __restrict__ Cf, __half* __restrict__ Ch,
    const float* __restrict__ bias,
    int K, int ldA, int ldB, int ldC,
    size_t strA, size_t strB, size_t strC) {
    extern __shared__ char dsm[];
    const uint32_t sbase = smem_u32(dsm);
    const int tid = threadIdx.x, lane = tid & 31, wid = tid >> 5;
    const int bx = blockIdx.x;
    const int by = CAUSAL ? (gridDim.y - 1 - blockIdx.y) : blockIdx.y;
    const int bz = blockIdx.z;
    const int m0 = by * 128, n0 = bx * 128;

    Ag += (size_t)bz * strA;
    Bg += (size_t)bz * strB;

    const int nk = CAUSAL ? (by + 1) * 2 : (K >> 6);   // 64-k chunks

    auto load_stage = [&](int buf, int chunk) {
        const uint32_t st = sbase + buf * STG;
        const int k0 = chunk * 64;
        // A: 128 rows x 128B, as two 64B sub-tiles; 1024 x 16B, 4/thread
        #pragma unroll
        for (int i = 0; i < 4; i++) {
            const int j = tid + 256 * i;
            const int row = j >> 3, c = j & 7;           // c: 16B chunk in row
            const int sub = c >> 2, cc = c & 3;          // k-half, chunk within
            cp16(st + sub * OFF_A1 + row * 80 + cc * 16,
                 Ag + (size_t)(m0 + row) * ldA + k0 + sub * 32 + cc * 8);
        }
        // B: 64 rows x 256B; 1024 x 16B, 4/thread
        #pragma unroll
        for (int i = 0; i < 4; i++) {
            const int j = tid + 256 * i;
            const int row = j >> 4, c = j & 15;
            cp16(st + OFF_B + row * 272 + c * 16,
                 Bg + (size_t)(k0 + row) * ldB + n0 + c * 8);
        }
    };

    float acc[4][4][4];
    #pragma unroll
    for (int i = 0; i < 4; i++)
        #pragma unroll
        for (int j = 0; j < 4; j++)
            #pragma unroll
            for (int t = 0; t < 4; t++) acc[i][j][t] = 0.f;

    const int wm = (wid >> 2) * 64;      // warp m-offset within CTA
    const int wn = (wid & 3) * 32;       // warp n-offset within CTA

    // prologue: both stages (nk >= 2 always)
    load_stage(0, 0); CP_COMMIT();
    load_stage(1, 1); CP_COMMIT();

    for (int kt = 0; kt < nk; kt++) {
        CP_WAIT1();                 // chunk kt resident
        __syncthreads();

        const uint32_t st = sbase + (kt & 1) * STG;
        #pragma unroll
        for (int kk = 0; kk < 4; kk++) {                 // 4 x k16 per chunk
            const int sub = kk >> 1;                     // A k-half sub-tile
            const int k16 = (kk & 1) * 16;               // k16 within sub-tile
            const int bk16 = kk * 16;                    // k16 within B tile
            uint32_t a_r[4][4], b_r[4][2];
            #pragma unroll
            for (int mt = 0; mt < 4; mt++) {
                uint32_t off = sub * OFF_A1 +
                               ((wm + mt * 16 + (lane & 15)) * 80 +
                                (k16 + (lane >> 4) * 8) * 2);
                ldsm_x4(a_r[mt], st + off);
            }
            #pragma unroll
            for (int np = 0; np < 2; np++) {
                uint32_t off = ((bk16 + (lane & 15)) * 272 +
                                (wn + np * 16 + (lane >> 4) * 8) * 2);
                uint32_t t4[4];
                ldsm_x4_t(t4, st + OFF_B + off);
                b_r[np * 2][0] = t4[0]; b_r[np * 2][1] = t4[1];
                b_r[np * 2 + 1][0] = t4[2]; b_r[np * 2 + 1][1] = t4[3];
            }
            #pragma unroll
            for (int mt = 0; mt < 4; mt++)
                #pragma unroll
                for (int nt = 0; nt < 4; nt++)
                    mma_f16(acc[mt][nt], a_r[mt], b_r[nt]);
        }
        __syncthreads();            // stage fully consumed before refill
        if (kt + 2 < nk) load_stage(kt & 1, kt + 2);
        CP_COMMIT();                // always commit (possibly empty group)
    }

    // epilogue
    const int gr = lane >> 2, gc = (lane & 3) * 2;
    #pragma unroll
    for (int mt = 0; mt < 4; mt++) {
        const int mrow = m0 + wm + mt * 16 + gr;
        #pragma unroll
        for (int nt = 0; nt < 4; nt++) {
            const int ncol = n0 + wn + nt * 8 + gc;
            #pragma unroll
            for (int h = 0; h < 2; h++) {
                const int r = mrow + h * 8;
                float v0 = acc[mt][nt][h * 2 + 0];
                float v1 = acc[mt][nt][h * 2 + 1];
                if (HALF_EPI) {
                    const float2 bb = *reinterpret_cast<const float2*>(bias + ncol);
                    v0 += bb.x; v1 += bb.y;
                    uint32_t hp = (uint32_t)__half_as_ushort(__float2half_rn(v0)) |
                                  ((uint32_t)__half_as_ushort(__float2half_rn(v1)) << 16);
                    *reinterpret_cast<uint32_t*>(Ch + (size_t)r * ldC + ncol) = hp;
                } else {
                    float2 o; o.x = v0; o.y = v1;
                    *reinterpret_cast<float2*>(Cf + (size_t)bz * strC +
                                               (size_t)r * ldC + ncol) = o;
                }
            }
        }
    }
}

// ---------------------------------------------------------------------------
extern "C" void kernel_launch(void* const* d_in, const int* in_sizes, int n_in,
                              void* d_out, int out_size) {
    const float* hs    = (const float*)d_in[0];   // [B,S,HID]
    const float* assoc = (const float*)d_in[1];   // [B,S,S]
    // d_in[2] = broad_hc_attn (unused: broad_heads == 0)
    const float* Wv    = (const float*)d_in[3];   // [HID, NH*HD]
    const float* bv    = (const float*)d_in[4];   // [NH*HD]
    float*       out   = (float*)d_out;           // [B,S,NH*HD]
    (void)in_sizes; (void)n_in; (void)out_size;

    // one-time side stream + events for fork-join overlap (no device memory)
    static cudaStream_t s2 = nullptr;
    static cudaEvent_t ev1 = nullptr, ev2 = nullptr;
    if (s2 == nullptr) {
        cudaStreamCreateWithFlags(&s2, cudaStreamNonBlocking);
        cudaEventCreateWithFlags(&ev1, cudaEventDisableTiming);
        cudaEventCreateWithFlags(&ev2, cudaEventDisableTiming);
    }

    cudaFuncSetAttribute(mma_gemm<false, true>,
                         cudaFuncAttributeMaxDynamicSharedMemorySize, GEMM_SMEM);
    cudaFuncSetAttribute(mma_gemm<true, false>,
                         cudaFuncAttributeMaxDynamicSharedMemorySize, GEMM_SMEM);

    __half *hs_h, *wv_h, *at_h, *v_h;
    cudaGetSymbolAddress((void**)&hs_h, g_hs_h);
    cudaGetSymbolAddress((void**)&wv_h, g_wv_h);
    cudaGetSymbolAddress((void**)&at_h, g_at_h);
    cudaGetSymbolAddress((void**)&v_h, g_v_h);

    // fork: attn prep (rowsum + normalize + mask + fp16) on side stream,
    // overlapped with the GEMM1 dependency chain on the main stream.
    cudaEventRecord(ev1, 0);
    cudaStreamWaitEvent(s2, ev1, 0);
    attn_prep<<<B_ * S_, 256, 0, s2>>>(assoc);
    cudaEventRecord(ev2, s2);

    // main stream: hs fp16 convert, Wv fp16 convert, GEMM1 (full batched grid)
    split_hi<<<(int)(((size_t)B_ * S_ * HID_ / 4) / 256), 256>>>(hs, hs_h);
    split_hi<<<(int)(((size_t)HID_ * NHD_ / 4) / 256), 256>>>(Wv, wv_h);
    mma_gemm<false, true><<<dim3(NHD_ / 128, (B_ * S_) / 128, 1), 256, GEMM_SMEM>>>(
        hs_h, wv_h, nullptr, v_h, bv,
        HID_, HID_, NHD_, NHD_, 0, 0, 0);

    // join, then GEMM2 (causal k-truncation, heavy blocks first)
    cudaStreamWaitEvent(0, ev2, 0);
    mma_gemm<true, false><<<dim3(NHD_ / 128, S_ / 128, B_), 256, GEMM_SMEM>>>(
        at_h, v_h, out, nullptr, nullptr,
        S_, S_, NHD_, NHD_,
        (size_t)S_ * S_, (size_t)S_ * NHD_, (size_t)S_ * NHD_);
}

// round 13
// speedup vs baseline: 2.7477x; 1.3253x over previous
#include <cuda_runtime.h>
#include <cuda_fp16.h>
#include <cstdint>

#define B_   4
#define S_   2048
#define HID_ 1024
#define NHD_ 1024
#define EPS_ 1e-6f

// ---------------------------------------------------------------------------
// Packed-tile geometry: global operands stored as EXACT images of the smem
// stage, so one cp.async.bulk per tile replaces 2048 cp.async.cg issues.
//   A tile: 2 k-sub x 128 rows x 80B (64B data + 16B pad)  = 20480 B
//   B tile: 64 rows x 272B (256B data + 16B pad)           = 17408 B
// ---------------------------------------------------------------------------
#define A_TILE_B 20480
#define B_TILE_B 17408
#define ATPK_BATCH ((size_t)16 * 32 * A_TILE_B)   // attn packed, per batch
#define VPK_BATCH  ((size_t)8  * 32 * B_TILE_B)   // value packed, per batch

__device__ __align__(16) unsigned char g_hs_pk[(size_t)64 * 16 * A_TILE_B]; // 21.0 MB
__device__ __align__(16) unsigned char g_wv_pk[(size_t)8  * 16 * B_TILE_B]; //  2.2 MB
__device__ __align__(16) unsigned char g_at_pk[(size_t)B_ * ATPK_BATCH];    // 41.9 MB
__device__ __align__(16) unsigned char g_v_pk [(size_t)B_ * VPK_BATCH];     // 17.8 MB

// ---------------------------------------------------------------------------
// Helpers (plain-sm_103-legal: cp.async.bulk / mbarrier / ldmatrix / mma.sync)
// ---------------------------------------------------------------------------
__device__ __forceinline__ uint32_t smem_u32(const void* p) {
    uint32_t a;
    asm("{ .reg .u64 t; cvta.to.shared.u64 t, %1; cvt.u32.u64 %0, t; }"
        : "=r"(a) : "l"(p));
    return a;
}
#define MBARRIER_INIT(addr, cnt) \
    asm volatile("mbarrier.init.shared.b64 [%0], %1;" :: "r"(addr), "r"(cnt) : "memory")
#define MBARRIER_EXPECT_TX(addr, bytes) \
    asm volatile("mbarrier.arrive.expect_tx.shared.b64 _, [%0], %1;" \
                 :: "r"(addr), "r"((uint32_t)(bytes)) : "memory")
#define MBARRIER_WAIT_PARITY(mbar_smem_addr, phase_parity) do { \
    uint32_t _mbar = (uint32_t)(mbar_smem_addr); \
    uint32_t _parity = (uint32_t)(phase_parity); \
    uint32_t _done; \
    asm volatile( \
        "{\n\t.reg .pred p;\n\t" \
        "mbarrier.try_wait.parity.acquire.cta.shared::cta.b64 p, [%1], %2;\n\t" \
        "selp.b32 %0, 1, 0, p;\n\t}" \
        : "=r"(_done) : "r"(_mbar), "r"(_parity) : "memory"); \
    if (!_done) { \
        asm volatile( \
            "{\n\t.reg .pred P1;\n\t" \
            "WAIT_LOOP_%=:\n\t" \
            "mbarrier.try_wait.parity.acquire.cta.shared::cta.b64 P1, [%0], %1, 0x989680;\n\t" \
            "@P1 bra.uni WAIT_DONE_%=;\n\t" \
            "bra.uni WAIT_LOOP_%=;\n\t" \
            "WAIT_DONE_%=:\n\t}" \
            :: "r"(_mbar), "r"(_parity) : "memory"); \
    } \
} while (0)

__device__ __forceinline__ void bulk_cp(uint32_t dst, const void* src,
                                        uint32_t bytes, uint32_t mbar) {
    asm volatile(
        "cp.async.bulk.shared::cluster.global.mbarrier::complete_tx::bytes "
        "[%0], [%1], %2, [%3];"
        :: "r"(dst), "l"(src), "r"(bytes), "r"(mbar) : "memory");
}

__device__ __forceinline__ void ldsm_x4(uint32_t* r, uint32_t a) {
    asm volatile("ldmatrix.sync.aligned.m8n8.x4.shared.b16 {%0,%1,%2,%3}, [%4];"
                 : "=r"(r[0]), "=r"(r[1]), "=r"(r[2]), "=r"(r[3]) : "r"(a));
}
__device__ __forceinline__ void ldsm_x4_t(uint32_t* r, uint32_t a) {
    asm volatile("ldmatrix.sync.aligned.m8n8.x4.trans.shared.b16 {%0,%1,%2,%3}, [%4];"
                 : "=r"(r[0]), "=r"(r[1]), "=r"(r[2]), "=r"(r[3]) : "r"(a));
}
__device__ __forceinline__ void mma_f16(float* c, const uint32_t* a, const uint32_t* b) {
    asm volatile(
        "mma.sync.aligned.m16n8k16.row.col.f32.f16.f16.f32 "
        "{%0,%1,%2,%3}, {%4,%5,%6,%7}, {%8,%9}, {%0,%1,%2,%3};"
        : "+f"(c[0]), "+f"(c[1]), "+f"(c[2]), "+f"(c[3])
        : "r"(a[0]), "r"(a[1]), "r"(a[2]), "r"(a[3]), "r"(b[0]), "r"(b[1]));
}

// ---------------------------------------------------------------------------
// Prep kernels — write PACKED tile layouts
// ---------------------------------------------------------------------------
// attn: rowsum + normalize + causal mask + fp16, packed A-tiles.
// Only writes k-tiles at/below the row's diagonal tile (all G2 ever reads).
__global__ __launch_bounds__(256) void attn_prep(const float* __restrict__ attn) {
    int row = blockIdx.x;              // b*S + q
    int b = row >> 11, q = row & (S_ - 1);
    const float* a = attn + (size_t)row * S_;
    float s = 0.f;
    for (int k = threadIdx.x; k <= q; k += 256) s += a[k];
    #pragma unroll
    for (int o = 16; o; o >>= 1) s += __shfl_down_sync(0xffffffffu, s, o);
    __shared__ float red[8];
    __shared__ float sinv;
    if ((threadIdx.x & 31) == 0) red[threadIdx.x >> 5] = s;
    __syncthreads();
    if (threadIdx.x == 0) {
        float t = 0.f;
        #pragma unroll
        for (int i = 0; i < 8; i++) t += red[i];
        sinv = 1.f / (EPS_ + t);
    }
    __syncthreads();
    float inv = sinv;
    unsigned char* base = g_at_pk + (size_t)b * ATPK_BATCH +
                          (size_t)(q >> 7) * 32 * A_TILE_B;
    const int row80 = (q & 127) * 80;
    const int climit = ((q >> 7) + 1) * 32;   // 4-col groups up to diag tile end
    for (int c = threadIdx.x; c < climit; c += 256) {
        int k = c * 4;
        float4 v = *reinterpret_cast<const float4*>(a + k);
        ushort4 o;
        o.x = __half_as_ushort(__float2half_rn((k + 0 <= q) ? v.x * inv : 0.f));
        o.y = __half_as_ushort(__float2half_rn((k + 1 <= q) ? v.y * inv : 0.f));
        o.z = __half_as_ushort(__float2half_rn((k + 2 <= q) ? v.z * inv : 0.f));
        o.w = __half_as_ushort(__float2half_rn((k + 3 <= q) ? v.w * inv : 0.f));
        unsigned char* p = base + (size_t)(k >> 6) * A_TILE_B +
                           ((k >> 5) & 1) * 10240 + row80 + (k & 31) * 2;
        *reinterpret_cast<ushort4*>(p) = o;
    }
}

// hidden_states fp32 -> fp16, packed A-tiles (m flat over B*S)
__global__ __launch_bounds__(256) void pack_hs(const float* __restrict__ src) {
    size_t i = (size_t)blockIdx.x * 256 + threadIdx.x;   // float4 index
    float4 v = reinterpret_cast<const float4*>(src)[i];
    size_t e = i * 4;
    int s = (int)(e >> 10), k = (int)(e & 1023);
    ushort4 H;
    H.x = __half_as_ushort(__float2half_rn(v.x));
    H.y = __half_as_ushort(__float2half_rn(v.y));
    H.z = __half_as_ushort(__float2half_rn(v.z));
    H.w = __half_as_ushort(__float2half_rn(v.w));
    unsigned char* p = g_hs_pk +
        ((size_t)(s >> 7) * 16 + (k >> 6)) * A_TILE_B +
        ((k >> 5) & 1) * 10240 + (s & 127) * 80 + (k & 31) * 2;
    *reinterpret_cast<ushort4*>(p) = H;
}

// Wv [K][N] fp32 -> fp16, packed B-tiles
__global__ __launch_bounds__(256) void pack_wv(const float* __restrict__ src) {
    size_t i = (size_t)blockIdx.x * 256 + threadIdx.x;   // float4 index
    float4 v = reinterpret_cast<const float4*>(src)[i];
    size_t e = i * 4;
    int kr = (int)(e >> 10), nc = (int)(e & 1023);
    ushort4 H;
    H.x = __half_as_ushort(__float2half_rn(v.x));
    H.y = __half_as_ushort(__float2half_rn(v.y));
    H.z = __half_as_ushort(__float2half_rn(v.z));
    H.w = __half_as_ushort(__float2half_rn(v.w));
    unsigned char* p = g_wv_pk +
        ((size_t)(nc >> 7) * 16 + (kr >> 6)) * B_TILE_B +
        (kr & 63) * 272 + (nc & 127) * 2;
    *reinterpret_cast<ushort4*>(p) = H;
}

// ---------------------------------------------------------------------------
// HMMA GEMM: C[m,n] = sum_k A[m,k]*B[k,n]  (fp16, fp32 acc)
// 128x128 CTA tile, BK=64, 8 warps (64x32), 2-stage bulk-copy pipeline,
// 2 CTAs/SM. Inner loop identical to R11; loads are 2 bulk copies per chunk.
// ---------------------------------------------------------------------------
static constexpr int OFF_A1 = 10240;
static constexpr int OFF_B  = 20480;
static constexpr int STG = 37888;            // == A_TILE_B + B_TILE_B
static constexpr int GEMM_SMEM = 2 * STG + 256;   // stages + mbarriers + align

template <bool CAUSAL, bool PACK_EPI>
__global__ __launch_bounds__(256, 2) void mma_gemm(
    const unsigned char* __restrict__ Apk, const unsigned char* __restrict__ Bpk,
    float* __restrict__ Cf, unsigned char* __restrict__ Vpk,
    const float* __restrict__ bias,
    int nkTot, size_t strA_b, size_t strB_b, size_t strC) {
    extern __shared__ char dsm[];
    const uint32_t sb = (smem_u32(dsm) + 127) & ~127u;
    const uint32_t mb0 = sb + 2 * STG, mb1 = sb + 2 * STG + 8;
    const int tid = threadIdx.x, lane = tid & 31, wid = tid >> 5;
    const int bx = blockIdx.x;
    const int by = CAUSAL ? (gridDim.y - 1 - blockIdx.y) : blockIdx.y;
    const int bz = blockIdx.z;
    const int m0 = by * 128, n0 = bx * 128;

    const unsigned char* Abase = Apk + (size_t)bz * strA_b +
                                 (size_t)by * nkTot * A_TILE_B;
    const unsigned char* Bbase = Bpk + (size_t)bz * strB_b +
                                 (size_t)bx * nkTot * B_TILE_B;

    const int nk = CAUSAL ? (by + 1) * 2 : nkTot;   // 64-k chunks (nk >= 2)

    if (tid == 0) { MBARRIER_INIT(mb0, 1); MBARRIER_INIT(mb1, 1); }
    __syncthreads();

    float acc[4][4][4];
    #pragma unroll
    for (int i = 0; i < 4; i++)
        #pragma unroll
        for (int j = 0; j < 4; j++)
            #pragma unroll
            for (int t = 0; t < 4; t++) acc[i][j][t] = 0.f;

    const int wm = (wid >> 2) * 64;
    const int wn = (wid & 3) * 32;

    // prologue: both stages
    if (tid == 0) {
        MBARRIER_EXPECT_TX(mb0, STG);
        bulk_cp(sb,         Abase, A_TILE_B, mb0);
        bulk_cp(sb + OFF_B, Bbase, B_TILE_B, mb0);
        MBARRIER_EXPECT_TX(mb1, STG);
        bulk_cp(sb + STG,         Abase + A_TILE_B, A_TILE_B, mb1);
        bulk_cp(sb + STG + OFF_B, Bbase + B_TILE_B, B_TILE_B, mb1);
    }

    for (int kt = 0; kt < nk; kt++) {
        MBARRIER_WAIT_PARITY((kt & 1) ? mb1 : mb0, (kt >> 1) & 1);

        const uint32_t st = sb + (kt & 1) * STG;
        #pragma unroll
        for (int kk = 0; kk < 4; kk++) {
            const int sub = kk >> 1;
            const int k16 = (kk & 1) * 16;
            const int bk16 = kk * 16;
            uint32_t a_r[4][4], b_r[4][2];
            #pragma unroll
            for (int mt = 0; mt < 4; mt++) {
                uint32_t off = sub * OFF_A1 +
                               ((wm + mt * 16 + (lane & 15)) * 80 +
                                (k16 + (lane >> 4) * 8) * 2);
                ldsm_x4(a_r[mt], st + off);
            }
            #pragma unroll
            for (int np = 0; np < 2; np++) {
                uint32_t off = ((bk16 + (lane & 15)) * 272 +
                                (wn + np * 16 + (lane >> 4) * 8) * 2);
                uint32_t t4[4];
                ldsm_x4_t(t4, st + OFF_B + off);
                b_r[np * 2][0] = t4[0]; b_r[np * 2][1] = t4[1];
                b_r[np * 2 + 1][0] = t4[2]; b_r[np * 2 + 1][1] = t4[3];
            }
            #pragma unroll
            for (int mt = 0; mt < 4; mt++)
                #pragma unroll
                for (int nt = 0; nt < 4; nt++)
                    mma_f16(acc[mt][nt], a_r[mt], b_r[nt]);
        }
        __syncthreads();            // stage consumed by all warps
        if (tid == 0 && kt + 2 < nk) {
            const uint32_t mb = (kt & 1) ? mb1 : mb0;
            const uint32_t dst = sb + (kt & 1) * STG;
            MBARRIER_EXPECT_TX(mb, STG);
            bulk_cp(dst,         Abase + (size_t)(kt + 2) * A_TILE_B, A_TILE_B, mb);
            bulk_cp(dst + OFF_B, Bbase + (size_t)(kt + 2) * B_TILE_B, B_TILE_B, mb);
        }
    }

    // epilogue
    const int gr = lane >> 2, gc = (lane & 3) * 2;
    #pragma unroll
    for (int mt = 0; mt < 4; mt++) {
        #pragma unroll
        for (int nt = 0; nt < 4; nt++) {
            const int col_in = wn + nt * 8 + gc;
            #pragma unroll
            for (int h = 0; h < 2; h++) {
                const int r = m0 + wm + mt * 16 + gr + h * 8;
                float v0 = acc[mt][nt][h * 2 + 0];
                float v1 = acc[mt][nt][h * 2 + 1];
                if (PACK_EPI) {
                    // write value in packed-B-tile format for GEMM2
                    const float2 bb =
                        *reinterpret_cast<const float2*>(bias + n0 + col_in);
                    v0 += bb.x; v1 += bb.y;
                    uint32_t hp =
                        (uint32_t)__half_as_ushort(__float2half_rn(v0)) |
                        ((uint32_t)__half_as_ushort(__float2half_rn(v1)) << 16);
                    const int b = r >> 11, r_b = r & 2047;
                    const int kc = r_b >> 6, ri = r_b & 63;
                    unsigned char* p = Vpk + (size_t)b * VPK_BATCH +
                                       (size_t)(bx * 32 + kc) * B_TILE_B +
                                       ri * 272 + col_in * 2;
                    *reinterpret_cast<uint32_t*>(p) = hp;
                } else {
                    float2 o; o.x = v0; o.y = v1;
                    *reinterpret_cast<float2*>(Cf + (size_t)bz * strC +
                                               (size_t)r * NHD_ + n0 + col_in) = o;
                }
            }
        }
    }
}

// ---------------------------------------------------------------------------
extern "C" void kernel_launch(void* const* d_in, const int* in_sizes, int n_in,
                              void* d_out, int out_size) {
    const float* hs    = (const float*)d_in[0];   // [B,S,HID]
    const float* assoc = (const float*)d_in[1];   // [B,S,S]
    // d_in[2] = broad_hc_attn (unused: broad_heads == 0)
    const float* Wv    = (const float*)d_in[3];   // [HID, NH*HD]
    const float* bv    = (const float*)d_in[4];   // [NH*HD]
    float*       out   = (float*)d_out;           // [B,S,NH*HD]
    (void)in_sizes; (void)n_in; (void)out_size;

    static cudaStream_t s2 = nullptr;
    static cudaEvent_t ev1 = nullptr, ev2 = nullptr;
    if (s2 == nullptr) {
        cudaStreamCreateWithFlags(&s2, cudaStreamNonBlocking);
        cudaEventCreateWithFlags(&ev1, cudaEventDisableTiming);
        cudaEventCreateWithFlags(&ev2, cudaEventDisableTiming);
    }

    cudaFuncSetAttribute(mma_gemm<false, true>,
                         cudaFuncAttributeMaxDynamicSharedMemorySize, GEMM_SMEM);
    cudaFuncSetAttribute(mma_gemm<true, false>,
                         cudaFuncAttributeMaxDynamicSharedMemorySize, GEMM_SMEM);

    unsigned char *hs_pk, *wv_pk, *at_pk, *v_pk;
    cudaGetSymbolAddress((void**)&hs_pk, g_hs_pk);
    cudaGetSymbolAddress((void**)&wv_pk, g_wv_pk);
    cudaGetSymbolAddress((void**)&at_pk, g_at_pk);
    cudaGetSymbolAddress((void**)&v_pk, g_v_pk);

    // fork: attn prep on side stream, overlapped with GEMM1's chain
    cudaEventRecord(ev1, 0);
    cudaStreamWaitEvent(s2, ev1, 0);
    attn_prep<<<B_ * S_, 256, 0, s2>>>(assoc);
    cudaEventRecord(ev2, s2);

    // main: pack hs + Wv, GEMM1 (value -> packed B-tiles)
    pack_hs<<<(int)(((size_t)B_ * S_ * HID_ / 4) / 256), 256>>>(hs);
    pack_wv<<<(int)(((size_t)HID_ * NHD_ / 4) / 256), 256>>>(Wv);
    mma_gemm<false, true><<<dim3(NHD_ / 128, (B_ * S_) / 128, 1), 256, GEMM_SMEM>>>(
        hs_pk, wv_pk, nullptr, v_pk, bv, 16, 0, 0, 0);

    // join, then GEMM2 (causal k-truncation, heavy blocks first)
    cudaStreamWaitEvent(0, ev2, 0);
    mma_gemm<true, false><<<dim3(NHD_ / 128, S_ / 128, B_), 256, GEMM_SMEM>>>(
        at_pk, v_pk, out, nullptr, nullptr,
        32, ATPK_BATCH, VPK_BATCH, (size_t)S_ * NHD_);
}